// round 3
// baseline (speedup 1.0000x reference)
#include <cuda_runtime.h>
#include <cuda_bf16.h>
#include <math.h>
#include <stdint.h>

// Problem dims
#define BB   4
#define LL   1024
#define DD   512
#define CHI  32
#define SS   4
#define NT   (BB*LL)          // 4096 tokens
#define CSC  (CHI*SS*CHI)     // 4096

// ---------------- scratch (__device__ globals, no allocs) ----------------
__device__ float g_site[(size_t)NT * CSC];   // x @ W_site + b_site        (64 MB)
__device__ float g_gate[(size_t)NT * DD];    // x @ W_gate + b_gate        (8 MB)
__device__ float g_Bmat[(size_t)NT * CHI * CHI]; // B_t stored [t][r*32+l] (16 MB)
__device__ float g_WB[512 * 1024];           // pre-reduced site weights for B
__device__ float g_bB[1024];                 // pre-reduced site bias for B
__device__ float g_c[(size_t)NT * CHI];      // c_t[r] = u_t @ B_t
__device__ float g_left[(size_t)NT * CHI];   // recorded left vectors
__device__ float g_M[(size_t)NT * (SS*CHI)]; // Mt flattened [t][128]
__device__ float g_y[(size_t)NT * DD];       // pre-LN y
__device__ float g_Wco[128 * 512];           // W_bridge @ W_out
__device__ float g_bco[512];                 // b_bridge @ W_out + b_out

// ---------------- prep: fuse bridge+out weights ----------------
__global__ void prep_kernel(const float* __restrict__ Wb, const float* __restrict__ bb,
                            const float* __restrict__ Wo, const float* __restrict__ bo)
{
    int idx = blockIdx.x * blockDim.x + threadIdx.x;   // 0..65535
    int pr = idx >> 9, j = idx & 511;
    float s = 0.f;
#pragma unroll
    for (int i = 0; i < 32; ++i)
        s = fmaf(Wb[pr * 32 + i], Wo[i * 512 + j], s);
    g_Wco[idx] = s;
    if (idx < 512) {
        float c = bo[idx];
#pragma unroll
        for (int i = 0; i < 32; ++i)
            c = fmaf(bb[i], Wo[i * 512 + idx], c);
        g_bco[idx] = c;
    }
}

// ---------------- prep: reduce W_site over physical index -> W_B ----------------
// site col index j = l*128 + p*32 + r;  W_B[d][r*32+l] = sum_p W_site[d][l*128+p*32+r]
__global__ __launch_bounds__(256) void wb_kernel(const float* __restrict__ Ws,
                                                 const float* __restrict__ bs)
{
    int idx = blockIdx.x * 256 + threadIdx.x;          // 0 .. 512*1024-1
    int d = idx >> 10, rem = idx & 1023;
    int l = rem >> 5, r = rem & 31;
    const float* p = Ws + (size_t)d * 4096 + l * 128 + r;   // coalesced in r
    g_WB[(size_t)d * 1024 + r * 32 + l] = p[0] + p[32] + p[64] + p[96];
    if (idx < 1024) {
        int ll = idx >> 5, rr = idx & 31;
        const float* q = bs + ll * 128 + rr;
        g_bB[rr * 32 + ll] = q[0] + q[32] + q[64] + q[96];
    }
}

// ---------------- tensor-core GEMM: C = A[MxK] @ B[KxN] + bias -------------
// bf16 3-term split (Ahi*Bhi + Ahi*Blo + Alo*Bhi) == ~fp32 accuracy.
// Tile 128x128, BK=32, 256 threads (8 warps as 2Mx4N), mma.m16n8k16.
#define SMSTRIDE 34
__device__ __forceinline__ void bf16split(float v, __nv_bfloat16& h, __nv_bfloat16& l)
{
    h = __float2bfloat16(v);
    l = __float2bfloat16(v - __bfloat162float(h));
}

#define MMA_BF16(d, a0, a1, a2, a3, b0, b1)                                   \
    asm volatile("mma.sync.aligned.m16n8k16.row.col.f32.bf16.bf16.f32 "       \
                 "{%0,%1,%2,%3}, {%4,%5,%6,%7}, {%8,%9}, {%0,%1,%2,%3};\n"    \
                 : "+f"(d[0]), "+f"(d[1]), "+f"(d[2]), "+f"(d[3])             \
                 : "r"(a0), "r"(a1), "r"(a2), "r"(a3), "r"(b0), "r"(b1))

__global__ __launch_bounds__(256, 1)
void hgemm_kernel(const float* __restrict__ A, const float* __restrict__ Bg,
                  const float* __restrict__ bias, float* __restrict__ C,
                  int M, int N, int K)
{
    __shared__ __nv_bfloat16 sAh[128][SMSTRIDE];
    __shared__ __nv_bfloat16 sAl[128][SMSTRIDE];
    __shared__ __nv_bfloat16 sBh[128][SMSTRIDE];   // transposed: [n][k]
    __shared__ __nv_bfloat16 sBl[128][SMSTRIDE];

    const int tid  = threadIdx.x;
    const int warp = tid >> 5;
    const int lane = tid & 31;
    const int g    = lane >> 2;          // 0..7
    const int tg   = lane & 3;           // 0..3
    const int m0w  = (warp >> 2) * 64;   // 0 | 64
    const int n0w  = (warp & 3) * 32;    // 0..96
    const int bm   = blockIdx.y * 128;
    const int bn   = blockIdx.x * 128;

    float acc[4][4][4];
#pragma unroll
    for (int i = 0; i < 4; ++i)
#pragma unroll
        for (int j = 0; j < 4; ++j)
#pragma unroll
            for (int e = 0; e < 4; ++e) acc[i][j][e] = 0.f;

    for (int k0 = 0; k0 < K; k0 += 32) {
        __syncthreads();
        // ---- load A tile 128x32 ----
#pragma unroll
        for (int q = 0; q < 4; ++q) {
            int i  = tid + 256 * q;          // 0..1023 float4s
            int r  = i >> 3;
            int c4 = (i & 7) * 4;
            float4 v = *(const float4*)(A + (size_t)(bm + r) * K + k0 + c4);
            __nv_bfloat16 h, l;
            bf16split(v.x, h, l); sAh[r][c4+0] = h; sAl[r][c4+0] = l;
            bf16split(v.y, h, l); sAh[r][c4+1] = h; sAl[r][c4+1] = l;
            bf16split(v.z, h, l); sAh[r][c4+2] = h; sAl[r][c4+2] = l;
            bf16split(v.w, h, l); sAh[r][c4+3] = h; sAl[r][c4+3] = l;
        }
        // ---- load B tile 32x128, store transposed [n][k] ----
#pragma unroll
        for (int q = 0; q < 4; ++q) {
            int i  = tid + 256 * q;
            int kr = i >> 5;
            int c4 = (i & 31) * 4;
            float4 v = *(const float4*)(Bg + (size_t)(k0 + kr) * N + bn + c4);
            __nv_bfloat16 h, l;
            bf16split(v.x, h, l); sBh[c4+0][kr] = h; sBl[c4+0][kr] = l;
            bf16split(v.y, h, l); sBh[c4+1][kr] = h; sBl[c4+1][kr] = l;
            bf16split(v.z, h, l); sBh[c4+2][kr] = h; sBl[c4+2][kr] = l;
            bf16split(v.w, h, l); sBh[c4+3][kr] = h; sBl[c4+3][kr] = l;
        }
        __syncthreads();

#pragma unroll
        for (int kk = 0; kk < 32; kk += 16) {
            uint32_t ah[4][4], al[4][4];
#pragma unroll
            for (int mi = 0; mi < 4; ++mi) {
                int row = m0w + mi * 16 + g;
                ah[mi][0] = *(const uint32_t*)&sAh[row    ][kk     + 2*tg];
                ah[mi][1] = *(const uint32_t*)&sAh[row + 8][kk     + 2*tg];
                ah[mi][2] = *(const uint32_t*)&sAh[row    ][kk + 8 + 2*tg];
                ah[mi][3] = *(const uint32_t*)&sAh[row + 8][kk + 8 + 2*tg];
                al[mi][0] = *(const uint32_t*)&sAl[row    ][kk     + 2*tg];
                al[mi][1] = *(const uint32_t*)&sAl[row + 8][kk     + 2*tg];
                al[mi][2] = *(const uint32_t*)&sAl[row    ][kk + 8 + 2*tg];
                al[mi][3] = *(const uint32_t*)&sAl[row + 8][kk + 8 + 2*tg];
            }
#pragma unroll
            for (int ni = 0; ni < 4; ++ni) {
                int col = n0w + ni * 8 + g;
                uint32_t bh0 = *(const uint32_t*)&sBh[col][kk     + 2*tg];
                uint32_t bh1 = *(const uint32_t*)&sBh[col][kk + 8 + 2*tg];
                uint32_t bl0 = *(const uint32_t*)&sBl[col][kk     + 2*tg];
                uint32_t bl1 = *(const uint32_t*)&sBl[col][kk + 8 + 2*tg];
#pragma unroll
                for (int mi = 0; mi < 4; ++mi) {
                    MMA_BF16(acc[mi][ni], ah[mi][0], ah[mi][1], ah[mi][2], ah[mi][3], bh0, bh1);
                    MMA_BF16(acc[mi][ni], ah[mi][0], ah[mi][1], ah[mi][2], ah[mi][3], bl0, bl1);
                    MMA_BF16(acc[mi][ni], al[mi][0], al[mi][1], al[mi][2], al[mi][3], bh0, bh1);
                }
            }
        }
    }

    // ---- epilogue with bias ----
#pragma unroll
    for (int mi = 0; mi < 4; ++mi) {
        int row = bm + m0w + mi * 16 + g;
#pragma unroll
        for (int ni = 0; ni < 4; ++ni) {
            int col = bn + n0w + ni * 8 + 2 * tg;
            float b0 = bias[col], b1 = bias[col + 1];
            float2 o0 = make_float2(acc[mi][ni][0] + b0, acc[mi][ni][1] + b1);
            float2 o1 = make_float2(acc[mi][ni][2] + b0, acc[mi][ni][3] + b1);
            *(float2*)&C[(size_t)row * N + col]       = o0;
            *(float2*)&C[(size_t)(row + 8) * N + col] = o1;
        }
    }
}

// ---------------- c_t[r] = sum_l u_t[l] * B_t[l][r] ----------------
__global__ void c_kernel(const float* __restrict__ x)
{
    int t = blockIdx.x;
    int r = threadIdx.x;                       // 0..31
    float u = x[(size_t)t * DD + r];           // lane l holds u_l
    const float* brow = g_Bmat + (size_t)t * 1024 + r * 32;
    float4 b4[8];
#pragma unroll
    for (int q = 0; q < 8; ++q) b4[q] = __ldg((const float4*)(brow + 4 * q));
    float c = 0.f;
#pragma unroll
    for (int q = 0; q < 8; ++q) {
        c = fmaf(__shfl_sync(0xffffffffu, u, 4 * q + 0), b4[q].x, c);
        c = fmaf(__shfl_sync(0xffffffffu, u, 4 * q + 1), b4[q].y, c);
        c = fmaf(__shfl_sync(0xffffffffu, u, 4 * q + 2), b4[q].z, c);
        c = fmaf(__shfl_sync(0xffffffffu, u, 4 * q + 3), b4[q].w, c);
    }
    g_c[(size_t)t * 32 + r] = c;
}

// ---------------- sequential scan: one warp per batch ----------------
// v_t = alpha_{t-1} * (v_{t-1} @ B_t) + c_t,  alpha = rsqrt(||v||^2 + 1e-24).
// Norm is accumulated from the SAME shfl broadcasts the matvec uses (no
// butterfly on the critical path).
__global__ void scan_kernel(const float* __restrict__ x)
{
    const int b = blockIdx.x;
    const int r = threadIdx.x;                 // 0..31
    const size_t tg0 = (size_t)b * LL;

    float v = 0.f;
    float4 bcur[8], bnxt[8];
    {
        const float* bp = g_Bmat + tg0 * 1024 + r * 32;
#pragma unroll
        for (int q = 0; q < 8; ++q) bcur[q] = __ldg((const float4*)(bp + 4 * q));
    }
    float ccur = g_c[tg0 * 32 + r];
    float ucur = x[tg0 * DD + r];

    for (int t = 0; t < LL; ++t) {
        const int tn = (t + 1 < LL) ? (t + 1) : t;
        const float* bpn = g_Bmat + (tg0 + tn) * 1024 + r * 32;
#pragma unroll
        for (int q = 0; q < 8; ++q) bnxt[q] = __ldg((const float4*)(bpn + 4 * q));
        float cnxt = g_c[(tg0 + tn) * 32 + r];
        float unxt = x[(tg0 + tn) * DD + r];

        float w0 = 0.f, w1 = 0.f, w2 = 0.f, w3 = 0.f;
        float s0 = 0.f, s1 = 0.f, s2 = 0.f, s3 = 0.f;
#pragma unroll
        for (int q = 0; q < 8; q += 4) {
            float va, vb, vc, vd;
            va = __shfl_sync(0xffffffffu, v, 4*q + 0);
            vb = __shfl_sync(0xffffffffu, v, 4*q + 1);
            vc = __shfl_sync(0xffffffffu, v, 4*q + 2);
            vd = __shfl_sync(0xffffffffu, v, 4*q + 3);
            w0 = fmaf(va, bcur[q].x, w0); s0 = fmaf(va, va, s0);
            w0 = fmaf(vb, bcur[q].y, w0); s0 = fmaf(vb, vb, s0);
            w0 = fmaf(vc, bcur[q].z, w0); s0 = fmaf(vc, vc, s0);
            w0 = fmaf(vd, bcur[q].w, w0); s0 = fmaf(vd, vd, s0);
            va = __shfl_sync(0xffffffffu, v, 4*q + 4);
            vb = __shfl_sync(0xffffffffu, v, 4*q + 5);
            vc = __shfl_sync(0xffffffffu, v, 4*q + 6);
            vd = __shfl_sync(0xffffffffu, v, 4*q + 7);
            w1 = fmaf(va, bcur[q+1].x, w1); s1 = fmaf(va, va, s1);
            w1 = fmaf(vb, bcur[q+1].y, w1); s1 = fmaf(vb, vb, s1);
            w1 = fmaf(vc, bcur[q+1].z, w1); s1 = fmaf(vc, vc, s1);
            w1 = fmaf(vd, bcur[q+1].w, w1); s1 = fmaf(vd, vd, s1);
            va = __shfl_sync(0xffffffffu, v, 4*q + 8);
            vb = __shfl_sync(0xffffffffu, v, 4*q + 9);
            vc = __shfl_sync(0xffffffffu, v, 4*q + 10);
            vd = __shfl_sync(0xffffffffu, v, 4*q + 11);
            w2 = fmaf(va, bcur[q+2].x, w2); s2 = fmaf(va, va, s2);
            w2 = fmaf(vb, bcur[q+2].y, w2); s2 = fmaf(vb, vb, s2);
            w2 = fmaf(vc, bcur[q+2].z, w2); s2 = fmaf(vc, vc, s2);
            w2 = fmaf(vd, bcur[q+2].w, w2); s2 = fmaf(vd, vd, s2);
            va = __shfl_sync(0xffffffffu, v, 4*q + 12);
            vb = __shfl_sync(0xffffffffu, v, 4*q + 13);
            vc = __shfl_sync(0xffffffffu, v, 4*q + 14);
            vd = __shfl_sync(0xffffffffu, v, 4*q + 15);
            w3 = fmaf(va, bcur[q+3].x, w3); s3 = fmaf(va, va, s3);
            w3 = fmaf(vb, bcur[q+3].y, w3); s3 = fmaf(vb, vb, s3);
            w3 = fmaf(vc, bcur[q+3].z, w3); s3 = fmaf(vc, vc, s3);
            w3 = fmaf(vd, bcur[q+3].w, w3); s3 = fmaf(vd, vd, s3);
        }
        float w = (w0 + w1) + (w2 + w3);
        float s = (s0 + s1) + (s2 + s3);

        float alpha = rsqrtf(s + 1e-24f);          // s==0 -> alpha*0 == 0
        g_left[(tg0 + t) * 32 + r] = fmaf(alpha, v, ucur);
        v = fmaf(alpha, w, ccur);

#pragma unroll
        for (int q = 0; q < 8; ++q) bcur[q] = bnxt[q];
        ccur = cnxt; ucur = unxt;
    }
}

// ---------------- recover Mt (== M, no truncation) per token ----------------
__global__ __launch_bounds__(128) void mrec_kernel()
{
    __shared__ float sleft[32];
    int t = blockIdx.x, tid = threadIdx.x;
    if (tid < 32) sleft[tid] = g_left[(size_t)t * 32 + tid];
    __syncthreads();
    const float* row = g_site + (size_t)t * CSC;
    float m = 0.f;
#pragma unroll
    for (int l = 0; l < 32; ++l)
        m = fmaf(sleft[l], __ldcs(row + l * 128 + tid), m);   // streaming, coalesced
    g_M[(size_t)t * 128 + tid] = m;
}

// ---------------- LayerNorm + sigmoid-gated residual ----------------
__global__ __launch_bounds__(256) void post_kernel(const float* __restrict__ x,
                                                   const float* __restrict__ gamma,
                                                   const float* __restrict__ beta,
                                                   float* __restrict__ out)
{
    __shared__ float red[256];
    int t = blockIdx.x, tid = threadIdx.x;
    size_t base = (size_t)t * DD;
    int j0 = tid, j1 = tid + 256;
    float y0 = g_y[base + j0], y1 = g_y[base + j1];

    red[tid] = y0 + y1;
    __syncthreads();
    for (int st = 128; st > 0; st >>= 1) {
        if (tid < st) red[tid] += red[tid + st];
        __syncthreads();
    }
    float mu = red[0] * (1.f / 512.f);
    __syncthreads();

    float d0 = y0 - mu, d1 = y1 - mu;
    red[tid] = d0 * d0 + d1 * d1;
    __syncthreads();
    for (int st = 128; st > 0; st >>= 1) {
        if (tid < st) red[tid] += red[tid + st];
        __syncthreads();
    }
    float var = red[0] * (1.f / 512.f);
    float rstd = rsqrtf(var + 1e-6f);

    float yn0 = d0 * rstd * gamma[j0] + beta[j0];
    float yn1 = d1 * rstd * gamma[j1] + beta[j1];
    float gl0 = g_gate[base + j0], gl1 = g_gate[base + j1];
    float gt0 = 1.f / (1.f + expf(-gl0));
    float gt1 = 1.f / (1.f + expf(-gl1));
    float xv0 = x[base + j0], xv1 = x[base + j1];
    out[base + j0] = gt0 * yn0 + (1.f - gt0) * xv0;
    out[base + j1] = gt1 * yn1 + (1.f - gt1) * xv1;
}

// ---------------- launch ----------------
extern "C" void kernel_launch(void* const* d_in, const int* in_sizes, int n_in,
                              void* d_out, int out_size)
{
    (void)in_sizes; (void)n_in; (void)out_size;
    const float* x       = (const float*)d_in[0];
    const float* W_site  = (const float*)d_in[1];
    const float* b_site  = (const float*)d_in[2];
    const float* W_bridge= (const float*)d_in[3];
    const float* b_bridge= (const float*)d_in[4];
    const float* W_out   = (const float*)d_in[5];
    const float* b_out   = (const float*)d_in[6];
    const float* gamma   = (const float*)d_in[7];
    const float* beta    = (const float*)d_in[8];
    const float* W_gate  = (const float*)d_in[9];
    const float* b_gate  = (const float*)d_in[10];
    float* out = (float*)d_out;

    static float *p_site = nullptr, *p_gate = nullptr, *p_M = nullptr,
                 *p_y = nullptr, *p_Wco = nullptr, *p_bco = nullptr,
                 *p_WB = nullptr, *p_bB = nullptr, *p_Bmat = nullptr;
    static cudaStream_t s1;
    static cudaEvent_t ev0, evS, evG;
    static bool inited = false;
    if (!inited) {
        cudaGetSymbolAddress((void**)&p_site, g_site);
        cudaGetSymbolAddress((void**)&p_gate, g_gate);
        cudaGetSymbolAddress((void**)&p_M,    g_M);
        cudaGetSymbolAddress((void**)&p_y,    g_y);
        cudaGetSymbolAddress((void**)&p_Wco,  g_Wco);
        cudaGetSymbolAddress((void**)&p_bco,  g_bco);
        cudaGetSymbolAddress((void**)&p_WB,   g_WB);
        cudaGetSymbolAddress((void**)&p_bB,   g_bB);
        cudaGetSymbolAddress((void**)&p_Bmat, g_Bmat);
        cudaStreamCreateWithFlags(&s1, cudaStreamNonBlocking);
        cudaEventCreateWithFlags(&ev0, cudaEventDisableTiming);
        cudaEventCreateWithFlags(&evS, cudaEventDisableTiming);
        cudaEventCreateWithFlags(&evG, cudaEventDisableTiming);
        inited = true;
    }

    // ---- fork side stream (captured as graph branch) ----
    cudaEventRecord(ev0, 0);
    cudaStreamWaitEvent(s1, ev0, 0);

    // side stream: fused bridge*out weights, site GEMM, gate GEMM
    prep_kernel<<<256, 256, 0, s1>>>(W_bridge, b_bridge, W_out, b_out);
    hgemm_kernel<<<dim3(CSC / 128, NT / 128), 256, 0, s1>>>(x, W_site, b_site, p_site, NT, CSC, DD);
    cudaEventRecord(evS, s1);
    hgemm_kernel<<<dim3(DD / 128, NT / 128), 256, 0, s1>>>(x, W_gate, b_gate, p_gate, NT, DD, DD);
    cudaEventRecord(evG, s1);

    // main stream: B-matrix path + sequential scan (independent of site GEMM)
    wb_kernel<<<2048, 256>>>(W_site, b_site);
    hgemm_kernel<<<dim3(1024 / 128, NT / 128), 256>>>(x, p_WB, p_bB, p_Bmat, NT, 1024, DD);
    c_kernel<<<NT, 32>>>(x);
    scan_kernel<<<BB, 32>>>(x);

    // join: need site for M recovery, then final GEMM
    cudaStreamWaitEvent(0, evS, 0);
    mrec_kernel<<<NT, 128>>>();
    hgemm_kernel<<<dim3(DD / 128, NT / 128), 256>>>(p_M, p_Wco, p_bco, p_y, NT, DD, 128);

    // join: need gate for the epilogue
    cudaStreamWaitEvent(0, evG, 0);
    post_kernel<<<NT, 256>>>(x, gamma, beta, out);
}

// round 5
// speedup vs baseline: 1.1202x; 1.1202x over previous
#include <cuda_runtime.h>
#include <cuda_bf16.h>
#include <math.h>
#include <stdint.h>

// Problem dims
#define BB   4
#define LL   1024
#define DD   512
#define CHI  32
#define SS   4
#define NT   (BB*LL)          // 4096 tokens
#define CSC  (CHI*SS*CHI)     // 4096

// ---------------- scratch (__device__ globals, no allocs) ----------------
__device__ float g_site[(size_t)NT * CSC];       // x @ W_site + b_site     (64 MB)
__device__ float g_gate[(size_t)NT * DD];        // x @ W_gate + b_gate
__device__ float g_Bmat[(size_t)NT * CHI * CHI]; // B_t stored [t][r*32+l]
__device__ float g_WB[512 * 1024];               // pre-reduced site weights (fp32)
__device__ float g_bB[1024];                     // pre-reduced site bias
__device__ float g_c[(size_t)NT * CHI];          // c_t[r] = u_t @ B_t
__device__ float g_left[(size_t)NT * CHI];       // recorded left vectors
__device__ float g_y[(size_t)NT * DD];           // pre-LN y
__device__ float g_Wco[128 * 512];               // W_bridge @ W_out (fp32)
__device__ float g_bco[512];                     // b_bridge @ W_out + b_out

// pre-converted bf16 split operands
__device__ __nv_bfloat16 g_xh[(size_t)NT * DD],   g_xl[(size_t)NT * DD];
__device__ __nv_bfloat16 g_WsT_h[(size_t)CSC * DD], g_WsT_l[(size_t)CSC * DD];   // [n][k]
__device__ __nv_bfloat16 g_WgT_h[DD * DD],        g_WgT_l[DD * DD];
__device__ __nv_bfloat16 g_WBT_h[1024 * DD],      g_WBT_l[1024 * DD];
__device__ __nv_bfloat16 g_WcoT_h[DD * 128],      g_WcoT_l[DD * 128];
__device__ __nv_bfloat16 g_mh[(size_t)NT * 128],  g_ml[(size_t)NT * 128];

// ---------------- helpers ----------------
__device__ __forceinline__ uint32_t smem_u32(const void* p) {
    uint32_t a;
    asm("{ .reg .u64 t; cvta.to.shared.u64 t, %1; cvt.u32.u64 %0, t; }" : "=r"(a) : "l"(p));
    return a;
}
__device__ __forceinline__ void bsplit(float v, __nv_bfloat16& h, __nv_bfloat16& l) {
    h = __float2bfloat16(v);
    l = __float2bfloat16(v - __bfloat162float(h));
}
#define CPA16(dst, src)  asm volatile("cp.async.cg.shared.global [%0], [%1], 16;" :: "r"(dst), "l"(src))
#define CPA_COMMIT()     asm volatile("cp.async.commit_group;" ::: "memory")
#define CPA_WAIT0()      asm volatile("cp.async.wait_group 0;" ::: "memory")
#define CPA_WAIT1()      asm volatile("cp.async.wait_group 1;" ::: "memory")

#define MMA_BF16(d, a0, a1, a2, a3, b0, b1)                                   \
    asm volatile("mma.sync.aligned.m16n8k16.row.col.f32.bf16.bf16.f32 "       \
                 "{%0,%1,%2,%3}, {%4,%5,%6,%7}, {%8,%9}, {%0,%1,%2,%3};\n"    \
                 : "+f"(d[0]), "+f"(d[1]), "+f"(d[2]), "+f"(d[3])             \
                 : "r"(a0), "r"(a1), "r"(a2), "r"(a3), "r"(b0), "r"(b1))

// ---------------- x -> bf16 split ----------------
__global__ void xcvt_kernel(const float* __restrict__ x)
{
    int i = blockIdx.x * 256 + threadIdx.x;      // NT*DD = 2M
    __nv_bfloat16 h, l;
    bsplit(x[i], h, l);
    g_xh[i] = h; g_xl[i] = l;
}

// ---------------- transpose + split: src[K][N] fp32 -> dh/dl[N][K] bf16 ----
__global__ void tsplit_kernel(const float* __restrict__ src,
                              __nv_bfloat16* __restrict__ dh,
                              __nv_bfloat16* __restrict__ dl, int K, int N)
{
    __shared__ float t[32][33];
    int bn = blockIdx.x * 32, bk = blockIdx.y * 32;
    int tx = threadIdx.x, ty = threadIdx.y;
#pragma unroll
    for (int i = ty; i < 32; i += 8)
        t[i][tx] = src[(size_t)(bk + i) * N + bn + tx];
    __syncthreads();
#pragma unroll
    for (int i = ty; i < 32; i += 8) {
        __nv_bfloat16 h, l;
        bsplit(t[tx][i], h, l);                  // = src[bk+tx][bn+i]
        dh[(size_t)(bn + i) * K + bk + tx] = h;
        dl[(size_t)(bn + i) * K + bk + tx] = l;
    }
}

// ---------------- prep: fuse bridge+out weights (fp32) ----------------
__global__ void prep_kernel(const float* __restrict__ Wb, const float* __restrict__ bb,
                            const float* __restrict__ Wo, const float* __restrict__ bo)
{
    int idx = blockIdx.x * blockDim.x + threadIdx.x;   // 0..65535
    int pr = idx >> 9, j = idx & 511;
    float s = 0.f;
#pragma unroll
    for (int i = 0; i < 32; ++i)
        s = fmaf(Wb[pr * 32 + i], Wo[i * 512 + j], s);
    g_Wco[idx] = s;
    if (idx < 512) {
        float c = bo[idx];
#pragma unroll
        for (int i = 0; i < 32; ++i)
            c = fmaf(bb[i], Wo[i * 512 + idx], c);
        g_bco[idx] = c;
    }
}

// ---------------- reduce W_site over physical index -> W_B (fp32) ----------
__global__ __launch_bounds__(256) void wb_kernel(const float* __restrict__ Ws,
                                                 const float* __restrict__ bs)
{
    int idx = blockIdx.x * 256 + threadIdx.x;          // 0 .. 512*1024-1
    int d = idx >> 10, rem = idx & 1023;
    int l = rem >> 5, r = rem & 31;
    const float* p = Ws + (size_t)d * 4096 + l * 128 + r;   // coalesced in r
    g_WB[(size_t)d * 1024 + r * 32 + l] = p[0] + p[32] + p[64] + p[96];
    if (idx < 1024) {
        int ll = idx >> 5, rr = idx & 31;
        const float* q = bs + ll * 128 + rr;
        g_bB[rr * 32 + ll] = q[0] + q[32] + q[64] + q[96];
    }
}

// ============ bf16-split tensor GEMM: C = A[MxK] @ B[KxN] + bias ===========
// A given split (Ah,Al) row-major [M][K]; B given split TRANSPOSED [N][K].
// 3-term: AhBh + AhBl + AlBh. Tile 128x128, BK=32, double-buffered cp.async.
// smem per stage: 4 arrays x 128 rows x 80B (64B data + 16B pad) = 40960B.
#define HG_SMEM (2 * 40960)

__device__ __forceinline__ void hg_load(uint32_t sb,
    const __nv_bfloat16* __restrict__ Ah, const __nv_bfloat16* __restrict__ Al,
    const __nv_bfloat16* __restrict__ Bh, const __nv_bfloat16* __restrict__ Bl,
    int bm, int bn, int K, int k0, int tid)
{
#pragma unroll
    for (int q = 0; q < 2; ++q) {
        int id = tid + 256 * q;                  // 0..511
        int r = id >> 2, c = id & 3;
        uint32_t so = (uint32_t)(r * 80 + c * 16);
        size_t goA = (size_t)(bm + r) * K + k0 + c * 8;
        size_t goB = (size_t)(bn + r) * K + k0 + c * 8;
        CPA16(sb + so,          Ah + goA);
        CPA16(sb + 10240 + so,  Al + goA);
        CPA16(sb + 20480 + so,  Bh + goB);
        CPA16(sb + 30720 + so,  Bl + goB);
    }
}

__device__ __forceinline__ void hg_compute(const char* ss, float acc[4][4][4],
                                           int m0w, int n0w, int g, int tg)
{
    const char* sa_h = ss;
    const char* sa_l = ss + 10240;
    const char* sb_h = ss + 20480;
    const char* sb_l = ss + 30720;
#pragma unroll
    for (int kk = 0; kk < 2; ++kk) {
        int kb = kk * 32 + tg * 4;               // byte offset within row
        uint32_t ah[4][4], al[4][4];
#pragma unroll
        for (int mi = 0; mi < 4; ++mi) {
            int r0 = m0w + mi * 16 + g;
            ah[mi][0] = *(const uint32_t*)(sa_h + r0 * 80 + kb);
            ah[mi][1] = *(const uint32_t*)(sa_h + (r0 + 8) * 80 + kb);
            ah[mi][2] = *(const uint32_t*)(sa_h + r0 * 80 + kb + 16);
            ah[mi][3] = *(const uint32_t*)(sa_h + (r0 + 8) * 80 + kb + 16);
            al[mi][0] = *(const uint32_t*)(sa_l + r0 * 80 + kb);
            al[mi][1] = *(const uint32_t*)(sa_l + (r0 + 8) * 80 + kb);
            al[mi][2] = *(const uint32_t*)(sa_l + r0 * 80 + kb + 16);
            al[mi][3] = *(const uint32_t*)(sa_l + (r0 + 8) * 80 + kb + 16);
        }
#pragma unroll
        for (int ni = 0; ni < 4; ++ni) {
            int n0 = n0w + ni * 8 + g;
            uint32_t bh0 = *(const uint32_t*)(sb_h + n0 * 80 + kb);
            uint32_t bh1 = *(const uint32_t*)(sb_h + n0 * 80 + kb + 16);
            uint32_t bl0 = *(const uint32_t*)(sb_l + n0 * 80 + kb);
            uint32_t bl1 = *(const uint32_t*)(sb_l + n0 * 80 + kb + 16);
#pragma unroll
            for (int mi = 0; mi < 4; ++mi) {
                MMA_BF16(acc[mi][ni], ah[mi][0], ah[mi][1], ah[mi][2], ah[mi][3], bh0, bh1);
                MMA_BF16(acc[mi][ni], ah[mi][0], ah[mi][1], ah[mi][2], ah[mi][3], bl0, bl1);
                MMA_BF16(acc[mi][ni], al[mi][0], al[mi][1], al[mi][2], al[mi][3], bh0, bh1);
            }
        }
    }
}

__global__ __launch_bounds__(256, 1)
void hgemm2_kernel(const __nv_bfloat16* __restrict__ Ah, const __nv_bfloat16* __restrict__ Al,
                   const __nv_bfloat16* __restrict__ Bh, const __nv_bfloat16* __restrict__ Bl,
                   const float* __restrict__ bias, float* __restrict__ C,
                   int M, int N, int K)
{
    extern __shared__ __align__(16) char smem[];
    const int tid = threadIdx.x;
    const int warp = tid >> 5, lane = tid & 31;
    const int g = lane >> 2, tg = lane & 3;
    const int m0w = (warp >> 2) * 64;            // 0 | 64
    const int n0w = (warp & 3) * 32;             // 0..96
    const int bm = blockIdx.y * 128, bn = blockIdx.x * 128;
    const uint32_t sb = smem_u32(smem);

    float acc[4][4][4];
#pragma unroll
    for (int i = 0; i < 4; ++i)
#pragma unroll
        for (int j = 0; j < 4; ++j)
#pragma unroll
            for (int e = 0; e < 4; ++e) acc[i][j][e] = 0.f;

    const int nk = K >> 5;
    hg_load(sb, Ah, Al, Bh, Bl, bm, bn, K, 0, tid);
    CPA_COMMIT();
    for (int i = 0; i < nk; ++i) {
        if (i + 1 < nk) {
            hg_load(sb + ((i + 1) & 1) * 40960, Ah, Al, Bh, Bl, bm, bn, K, (i + 1) * 32, tid);
            CPA_COMMIT();
            CPA_WAIT1();
        } else {
            CPA_WAIT0();
        }
        __syncthreads();
        hg_compute(smem + (i & 1) * 40960, acc, m0w, n0w, g, tg);
        __syncthreads();
    }

#pragma unroll
    for (int mi = 0; mi < 4; ++mi) {
        int row = bm + m0w + mi * 16 + g;
#pragma unroll
        for (int ni = 0; ni < 4; ++ni) {
            int col = bn + n0w + ni * 8 + 2 * tg;
            float b0 = bias[col], b1 = bias[col + 1];
            *(float2*)&C[(size_t)row * N + col] =
                make_float2(acc[mi][ni][0] + b0, acc[mi][ni][1] + b1);
            *(float2*)&C[(size_t)(row + 8) * N + col] =
                make_float2(acc[mi][ni][2] + b0, acc[mi][ni][3] + b1);
        }
    }
}

// ---------------- c_t[r] = sum_l u_t[l] * B_t[l][r] ----------------
__global__ void c_kernel(const float* __restrict__ x)
{
    int t = blockIdx.x;
    int r = threadIdx.x;                       // 0..31
    float u = x[(size_t)t * DD + r];           // lane l holds u_l
    const float* brow = g_Bmat + (size_t)t * 1024 + r * 32;
    float4 b4[8];
#pragma unroll
    for (int q = 0; q < 8; ++q) b4[q] = __ldg((const float4*)(brow + 4 * q));
    float c = 0.f;
#pragma unroll
    for (int q = 0; q < 8; ++q) {
        c = fmaf(__shfl_sync(0xffffffffu, u, 4 * q + 0), b4[q].x, c);
        c = fmaf(__shfl_sync(0xffffffffu, u, 4 * q + 1), b4[q].y, c);
        c = fmaf(__shfl_sync(0xffffffffu, u, 4 * q + 2), b4[q].z, c);
        c = fmaf(__shfl_sync(0xffffffffu, u, 4 * q + 3), b4[q].w, c);
    }
    g_c[(size_t)t * 32 + r] = c;
}

// ---------------- sequential scan: one warp per batch ----------------
__global__ void scan_kernel(const float* __restrict__ x)
{
    const int b = blockIdx.x;
    const int r = threadIdx.x;                 // 0..31
    const size_t tg0 = (size_t)b * LL;

    float v = 0.f;
    float4 bcur[8], bnxt[8];
    {
        const float* bp = g_Bmat + tg0 * 1024 + r * 32;
#pragma unroll
        for (int q = 0; q < 8; ++q) bcur[q] = __ldg((const float4*)(bp + 4 * q));
    }
    float ccur = g_c[tg0 * 32 + r];
    float ucur = x[tg0 * DD + r];

    for (int t = 0; t < LL; ++t) {
        const int tn = (t + 1 < LL) ? (t + 1) : t;
        const float* bpn = g_Bmat + (tg0 + tn) * 1024 + r * 32;
#pragma unroll
        for (int q = 0; q < 8; ++q) bnxt[q] = __ldg((const float4*)(bpn + 4 * q));
        float cnxt = g_c[(tg0 + tn) * 32 + r];
        float unxt = x[(tg0 + tn) * DD + r];

        float w0 = 0.f, w1 = 0.f, w2 = 0.f, w3 = 0.f;
        float s0 = 0.f, s1 = 0.f, s2 = 0.f, s3 = 0.f;
#pragma unroll
        for (int q = 0; q < 8; q += 4) {
            float va, vb, vc, vd;
            va = __shfl_sync(0xffffffffu, v, 4*q + 0);
            vb = __shfl_sync(0xffffffffu, v, 4*q + 1);
            vc = __shfl_sync(0xffffffffu, v, 4*q + 2);
            vd = __shfl_sync(0xffffffffu, v, 4*q + 3);
            w0 = fmaf(va, bcur[q].x, w0); s0 = fmaf(va, va, s0);
            w0 = fmaf(vb, bcur[q].y, w0); s0 = fmaf(vb, vb, s0);
            w0 = fmaf(vc, bcur[q].z, w0); s0 = fmaf(vc, vc, s0);
            w0 = fmaf(vd, bcur[q].w, w0); s0 = fmaf(vd, vd, s0);
            va = __shfl_sync(0xffffffffu, v, 4*q + 4);
            vb = __shfl_sync(0xffffffffu, v, 4*q + 5);
            vc = __shfl_sync(0xffffffffu, v, 4*q + 6);
            vd = __shfl_sync(0xffffffffu, v, 4*q + 7);
            w1 = fmaf(va, bcur[q+1].x, w1); s1 = fmaf(va, va, s1);
            w1 = fmaf(vb, bcur[q+1].y, w1); s1 = fmaf(vb, vb, s1);
            w1 = fmaf(vc, bcur[q+1].z, w1); s1 = fmaf(vc, vc, s1);
            w1 = fmaf(vd, bcur[q+1].w, w1); s1 = fmaf(vd, vd, s1);
            va = __shfl_sync(0xffffffffu, v, 4*q + 8);
            vb = __shfl_sync(0xffffffffu, v, 4*q + 9);
            vc = __shfl_sync(0xffffffffu, v, 4*q + 10);
            vd = __shfl_sync(0xffffffffu, v, 4*q + 11);
            w2 = fmaf(va, bcur[q+2].x, w2); s2 = fmaf(va, va, s2);
            w2 = fmaf(vb, bcur[q+2].y, w2); s2 = fmaf(vb, vb, s2);
            w2 = fmaf(vc, bcur[q+2].z, w2); s2 = fmaf(vc, vc, s2);
            w2 = fmaf(vd, bcur[q+2].w, w2); s2 = fmaf(vd, vd, s2);
            va = __shfl_sync(0xffffffffu, v, 4*q + 12);
            vb = __shfl_sync(0xffffffffu, v, 4*q + 13);
            vc = __shfl_sync(0xffffffffu, v, 4*q + 14);
            vd = __shfl_sync(0xffffffffu, v, 4*q + 15);
            w3 = fmaf(va, bcur[q+3].x, w3); s3 = fmaf(va, va, s3);
            w3 = fmaf(vb, bcur[q+3].y, w3); s3 = fmaf(vb, vb, s3);
            w3 = fmaf(vc, bcur[q+3].z, w3); s3 = fmaf(vc, vc, s3);
            w3 = fmaf(vd, bcur[q+3].w, w3); s3 = fmaf(vd, vd, s3);
        }
        float w = (w0 + w1) + (w2 + w3);
        float s = (s0 + s1) + (s2 + s3);

        float alpha = rsqrtf(s + 1e-24f);          // s==0 -> alpha*0 == 0
        g_left[(tg0 + t) * 32 + r] = fmaf(alpha, v, ucur);
        v = fmaf(alpha, w, ccur);

#pragma unroll
        for (int q = 0; q < 8; ++q) bcur[q] = bnxt[q];
        ccur = cnxt; ucur = unxt;
    }
}

// ------- recover Mt per token; emit bf16 split for the final GEMM ----------
__global__ __launch_bounds__(128) void mrec_kernel()
{
    __shared__ float sleft[32];
    int t = blockIdx.x, tid = threadIdx.x;
    if (tid < 32) sleft[tid] = g_left[(size_t)t * 32 + tid];
    __syncthreads();
    const float* row = g_site + (size_t)t * CSC;
    float m = 0.f;
#pragma unroll
    for (int l = 0; l < 32; ++l)
        m = fmaf(sleft[l], __ldcs(row + l * 128 + tid), m);   // streaming, coalesced
    __nv_bfloat16 h, lo;
    bsplit(m, h, lo);
    g_mh[(size_t)t * 128 + tid] = h;
    g_ml[(size_t)t * 128 + tid] = lo;
}

// ---------------- LayerNorm + sigmoid-gated residual ----------------
__global__ __launch_bounds__(256) void post_kernel(const float* __restrict__ x,
                                                   const float* __restrict__ gamma,
                                                   const float* __restrict__ beta,
                                                   float* __restrict__ out)
{
    __shared__ float red[256];
    int t = blockIdx.x, tid = threadIdx.x;
    size_t base = (size_t)t * DD;
    int j0 = tid, j1 = tid + 256;
    float y0 = g_y[base + j0], y1 = g_y[base + j1];

    red[tid] = y0 + y1;
    __syncthreads();
    for (int st = 128; st > 0; st >>= 1) {
        if (tid < st) red[tid] += red[tid + st];
        __syncthreads();
    }
    float mu = red[0] * (1.f / 512.f);
    __syncthreads();

    float d0 = y0 - mu, d1 = y1 - mu;
    red[tid] = d0 * d0 + d1 * d1;
    __syncthreads();
    for (int st = 128; st > 0; st >>= 1) {
        if (tid < st) red[tid] += red[tid + st];
        __syncthreads();
    }
    float var = red[0] * (1.f / 512.f);
    float rstd = rsqrtf(var + 1e-6f);

    float yn0 = d0 * rstd * gamma[j0] + beta[j0];
    float yn1 = d1 * rstd * gamma[j1] + beta[j1];
    float gl0 = g_gate[base + j0], gl1 = g_gate[base + j1];
    float gt0 = 1.f / (1.f + expf(-gl0));
    float gt1 = 1.f / (1.f + expf(-gl1));
    float xv0 = x[base + j0], xv1 = x[base + j1];
    out[base + j0] = gt0 * yn0 + (1.f - gt0) * xv0;
    out[base + j1] = gt1 * yn1 + (1.f - gt1) * xv1;
}

// ---------------- launch ----------------
extern "C" void kernel_launch(void* const* d_in, const int* in_sizes, int n_in,
                              void* d_out, int out_size)
{
    (void)in_sizes; (void)n_in; (void)out_size;
    const float* x       = (const float*)d_in[0];
    const float* W_site  = (const float*)d_in[1];
    const float* b_site  = (const float*)d_in[2];
    const float* W_bridge= (const float*)d_in[3];
    const float* b_bridge= (const float*)d_in[4];
    const float* W_out   = (const float*)d_in[5];
    const float* b_out   = (const float*)d_in[6];
    const float* gamma   = (const float*)d_in[7];
    const float* beta    = (const float*)d_in[8];
    const float* W_gate  = (const float*)d_in[9];
    const float* b_gate  = (const float*)d_in[10];
    float* out = (float*)d_out;

    static float *p_site, *p_gate, *p_y, *p_WB, *p_bB, *p_Wco, *p_bco, *p_Bmat;
    static __nv_bfloat16 *p_xh, *p_xl, *p_WsTh, *p_WsTl, *p_WgTh, *p_WgTl,
                         *p_WBTh, *p_WBTl, *p_WcoTh, *p_WcoTl, *p_mh, *p_ml;
    static cudaStream_t s1;
    static cudaEvent_t ev0, evS, evG;
    static bool inited = false;
    if (!inited) {
        cudaGetSymbolAddress((void**)&p_site,  g_site);
        cudaGetSymbolAddress((void**)&p_gate,  g_gate);
        cudaGetSymbolAddress((void**)&p_y,     g_y);
        cudaGetSymbolAddress((void**)&p_WB,    g_WB);
        cudaGetSymbolAddress((void**)&p_bB,    g_bB);
        cudaGetSymbolAddress((void**)&p_Wco,   g_Wco);
        cudaGetSymbolAddress((void**)&p_bco,   g_bco);
        cudaGetSymbolAddress((void**)&p_Bmat,  g_Bmat);
        cudaGetSymbolAddress((void**)&p_xh,    g_xh);
        cudaGetSymbolAddress((void**)&p_xl,    g_xl);
        cudaGetSymbolAddress((void**)&p_WsTh,  g_WsT_h);
        cudaGetSymbolAddress((void**)&p_WsTl,  g_WsT_l);
        cudaGetSymbolAddress((void**)&p_WgTh,  g_WgT_h);
        cudaGetSymbolAddress((void**)&p_WgTl,  g_WgT_l);
        cudaGetSymbolAddress((void**)&p_WBTh,  g_WBT_h);
        cudaGetSymbolAddress((void**)&p_WBTl,  g_WBT_l);
        cudaGetSymbolAddress((void**)&p_WcoTh, g_WcoT_h);
        cudaGetSymbolAddress((void**)&p_WcoTl, g_WcoT_l);
        cudaGetSymbolAddress((void**)&p_mh,    g_mh);
        cudaGetSymbolAddress((void**)&p_ml,    g_ml);
        cudaStreamCreateWithFlags(&s1, cudaStreamNonBlocking);
        cudaEventCreateWithFlags(&ev0, cudaEventDisableTiming);
        cudaEventCreateWithFlags(&evS, cudaEventDisableTiming);
        cudaEventCreateWithFlags(&evG, cudaEventDisableTiming);
        cudaFuncSetAttribute(hgemm2_kernel, cudaFuncAttributeMaxDynamicSharedMemorySize, HG_SMEM);
        inited = true;
    }

    // shared prologue: x split (both branches need it)
    xcvt_kernel<<<(NT * DD) / 256, 256>>>(x);
    cudaEventRecord(ev0, 0);
    cudaStreamWaitEvent(s1, ev0, 0);

    // ---- side stream: prep + weight converts + site & gate GEMMs ----
    prep_kernel<<<256, 256, 0, s1>>>(W_bridge, b_bridge, W_out, b_out);
    tsplit_kernel<<<dim3(16, 4),  dim3(32, 8), 0, s1>>>(p_Wco,  p_WcoTh, p_WcoTl, 128, 512);
    tsplit_kernel<<<dim3(128,16), dim3(32, 8), 0, s1>>>(W_site, p_WsTh,  p_WsTl,  512, 4096);
    tsplit_kernel<<<dim3(16, 16), dim3(32, 8), 0, s1>>>(W_gate, p_WgTh,  p_WgTl,  512, 512);
    hgemm2_kernel<<<dim3(CSC/128, NT/128), 256, HG_SMEM, s1>>>(
        p_xh, p_xl, p_WsTh, p_WsTl, b_site, p_site, NT, CSC, DD);
    cudaEventRecord(evS, s1);
    hgemm2_kernel<<<dim3(DD/128, NT/128), 256, HG_SMEM, s1>>>(
        p_xh, p_xl, p_WgTh, p_WgTl, b_gate, p_gate, NT, DD, DD);
    cudaEventRecord(evG, s1);

    // ---- main stream: B-matrix path + scan ----
    wb_kernel<<<2048, 256>>>(W_site, b_site);
    tsplit_kernel<<<dim3(32, 16), dim3(32, 8)>>>(p_WB, p_WBTh, p_WBTl, 512, 1024);
    hgemm2_kernel<<<dim3(1024/128, NT/128), 256, HG_SMEM>>>(
        p_xh, p_xl, p_WBTh, p_WBTl, p_bB, p_Bmat, NT, 1024, DD);
    c_kernel<<<NT, 32>>>(x);
    scan_kernel<<<BB, 32>>>(x);

    // join: site needed for M recovery, then final GEMM
    cudaStreamWaitEvent(0, evS, 0);
    mrec_kernel<<<NT, 128>>>();
    hgemm2_kernel<<<dim3(DD/128, NT/128), 256, HG_SMEM>>>(
        p_mh, p_ml, p_WcoTh, p_WcoTl, p_bco, p_y, NT, DD, 128);

    // join: gate needed for the epilogue
    cudaStreamWaitEvent(0, evG, 0);
    post_kernel<<<NT, 256>>>(x, gamma, beta, out);
}

// round 6
// speedup vs baseline: 1.5094x; 1.3474x over previous
#include <cuda_runtime.h>
#include <cuda_bf16.h>
#include <math.h>
#include <stdint.h>

// Problem dims
#define BB   4
#define LL   1024
#define DD   512
#define CHI  32
#define SS   4
#define NT   (BB*LL)          // 4096 tokens
#define CSC  (CHI*SS*CHI)     // 4096

// ---------------- scratch (__device__ globals, no allocs) ----------------
__device__ float g_site[(size_t)NT * CSC];       // x @ W_site + b_site     (64 MB)
__device__ float g_gate[(size_t)NT * DD];        // x @ W_gate + b_gate
__device__ float g_Bmat[(size_t)NT * CHI * CHI]; // B_t stored [t][r*32+l]
__device__ float g_WB[512 * 1024];               // pre-reduced site weights (fp32)
__device__ float g_bB[1024];                     // pre-reduced site bias
__device__ float g_c[(size_t)NT * CHI];          // c_t[r] = u_t @ B_t
__device__ float g_left[(size_t)NT * CHI];       // recorded left vectors
__device__ float g_y[(size_t)NT * DD];           // pre-LN y
__device__ float g_Wco[128 * 512];               // W_bridge @ W_out (fp32)
__device__ float g_bco[512];                     // b_bridge @ W_out + b_out

// pre-converted bf16 split operands
__device__ __nv_bfloat16 g_xh[(size_t)NT * DD],   g_xl[(size_t)NT * DD];
__device__ __nv_bfloat16 g_WsT_h[(size_t)CSC * DD], g_WsT_l[(size_t)CSC * DD];   // [n][k]
__device__ __nv_bfloat16 g_WgT_h[DD * DD],        g_WgT_l[DD * DD];
__device__ __nv_bfloat16 g_WBT_h[1024 * DD],      g_WBT_l[1024 * DD];
__device__ __nv_bfloat16 g_WcoT_h[DD * 128],      g_WcoT_l[DD * 128];
__device__ __nv_bfloat16 g_mh[(size_t)NT * 128],  g_ml[(size_t)NT * 128];

// ---------------- helpers ----------------
__device__ __forceinline__ uint32_t smem_u32(const void* p) {
    uint32_t a;
    asm("{ .reg .u64 t; cvta.to.shared.u64 t, %1; cvt.u32.u64 %0, t; }" : "=r"(a) : "l"(p));
    return a;
}
__device__ __forceinline__ void bsplit(float v, __nv_bfloat16& h, __nv_bfloat16& l) {
    h = __float2bfloat16(v);
    l = __float2bfloat16(v - __bfloat162float(h));
}
#define CPA16(dst, src)  asm volatile("cp.async.cg.shared.global [%0], [%1], 16;" :: "r"(dst), "l"(src))
#define CPA_COMMIT()     asm volatile("cp.async.commit_group;" ::: "memory")
#define CPA_WAIT0()      asm volatile("cp.async.wait_group 0;" ::: "memory")
#define CPA_WAIT1()      asm volatile("cp.async.wait_group 1;" ::: "memory")

#define MMA_BF16(d, a0, a1, a2, a3, b0, b1)                                   \
    asm volatile("mma.sync.aligned.m16n8k16.row.col.f32.bf16.bf16.f32 "       \
                 "{%0,%1,%2,%3}, {%4,%5,%6,%7}, {%8,%9}, {%0,%1,%2,%3};\n"    \
                 : "+f"(d[0]), "+f"(d[1]), "+f"(d[2]), "+f"(d[3])             \
                 : "r"(a0), "r"(a1), "r"(a2), "r"(a3), "r"(b0), "r"(b1))

// ---------------- x -> bf16 split ----------------
__global__ void xcvt_kernel(const float* __restrict__ x)
{
    int i = blockIdx.x * 256 + threadIdx.x;      // NT*DD = 2M
    __nv_bfloat16 h, l;
    bsplit(x[i], h, l);
    g_xh[i] = h; g_xl[i] = l;
}

// ---------------- transpose + split: src[K][N] fp32 -> dh/dl[N][K] bf16 ----
__global__ void tsplit_kernel(const float* __restrict__ src,
                              __nv_bfloat16* __restrict__ dh,
                              __nv_bfloat16* __restrict__ dl, int K, int N)
{
    __shared__ float t[32][33];
    int bn = blockIdx.x * 32, bk = blockIdx.y * 32;
    int tx = threadIdx.x, ty = threadIdx.y;
#pragma unroll
    for (int i = ty; i < 32; i += 8)
        t[i][tx] = src[(size_t)(bk + i) * N + bn + tx];
    __syncthreads();
#pragma unroll
    for (int i = ty; i < 32; i += 8) {
        __nv_bfloat16 h, l;
        bsplit(t[tx][i], h, l);                  // = src[bk+tx][bn+i]
        dh[(size_t)(bn + i) * K + bk + tx] = h;
        dl[(size_t)(bn + i) * K + bk + tx] = l;
    }
}

// ---------------- prep: fuse bridge+out weights (fp32) ----------------
__global__ void prep_kernel(const float* __restrict__ Wb, const float* __restrict__ bb,
                            const float* __restrict__ Wo, const float* __restrict__ bo)
{
    int idx = blockIdx.x * blockDim.x + threadIdx.x;   // 0..65535
    int pr = idx >> 9, j = idx & 511;
    float s = 0.f;
#pragma unroll
    for (int i = 0; i < 32; ++i)
        s = fmaf(Wb[pr * 32 + i], Wo[i * 512 + j], s);
    g_Wco[idx] = s;
    if (idx < 512) {
        float c = bo[idx];
#pragma unroll
        for (int i = 0; i < 32; ++i)
            c = fmaf(bb[i], Wo[i * 512 + idx], c);
        g_bco[idx] = c;
    }
}

// ---------------- reduce W_site over physical index -> W_B (fp32) ----------
__global__ __launch_bounds__(256) void wb_kernel(const float* __restrict__ Ws,
                                                 const float* __restrict__ bs)
{
    int idx = blockIdx.x * 256 + threadIdx.x;          // 0 .. 512*1024-1
    int d = idx >> 10, rem = idx & 1023;
    int l = rem >> 5, r = rem & 31;
    const float* p = Ws + (size_t)d * 4096 + l * 128 + r;   // coalesced in r
    g_WB[(size_t)d * 1024 + r * 32 + l] = p[0] + p[32] + p[64] + p[96];
    if (idx < 1024) {
        int ll = idx >> 5, rr = idx & 31;
        const float* q = bs + ll * 128 + rr;
        g_bB[rr * 32 + ll] = q[0] + q[32] + q[64] + q[96];
    }
}

// ============ bf16-split tensor GEMM: C = A[MxK] @ B[KxN] + bias ===========
#define HG_SMEM (2 * 40960)

__device__ __forceinline__ void hg_load(uint32_t sb,
    const __nv_bfloat16* __restrict__ Ah, const __nv_bfloat16* __restrict__ Al,
    const __nv_bfloat16* __restrict__ Bh, const __nv_bfloat16* __restrict__ Bl,
    int bm, int bn, int K, int k0, int tid)
{
#pragma unroll
    for (int q = 0; q < 2; ++q) {
        int id = tid + 256 * q;                  // 0..511
        int r = id >> 2, c = id & 3;
        uint32_t so = (uint32_t)(r * 80 + c * 16);
        size_t goA = (size_t)(bm + r) * K + k0 + c * 8;
        size_t goB = (size_t)(bn + r) * K + k0 + c * 8;
        CPA16(sb + so,          Ah + goA);
        CPA16(sb + 10240 + so,  Al + goA);
        CPA16(sb + 20480 + so,  Bh + goB);
        CPA16(sb + 30720 + so,  Bl + goB);
    }
}

__device__ __forceinline__ void hg_compute(const char* ss, float acc[4][4][4],
                                           int m0w, int n0w, int g, int tg)
{
    const char* sa_h = ss;
    const char* sa_l = ss + 10240;
    const char* sb_h = ss + 20480;
    const char* sb_l = ss + 30720;
#pragma unroll
    for (int kk = 0; kk < 2; ++kk) {
        int kb = kk * 32 + tg * 4;               // byte offset within row
        uint32_t ah[4][4], al[4][4];
#pragma unroll
        for (int mi = 0; mi < 4; ++mi) {
            int r0 = m0w + mi * 16 + g;
            ah[mi][0] = *(const uint32_t*)(sa_h + r0 * 80 + kb);
            ah[mi][1] = *(const uint32_t*)(sa_h + (r0 + 8) * 80 + kb);
            ah[mi][2] = *(const uint32_t*)(sa_h + r0 * 80 + kb + 16);
            ah[mi][3] = *(const uint32_t*)(sa_h + (r0 + 8) * 80 + kb + 16);
            al[mi][0] = *(const uint32_t*)(sa_l + r0 * 80 + kb);
            al[mi][1] = *(const uint32_t*)(sa_l + (r0 + 8) * 80 + kb);
            al[mi][2] = *(const uint32_t*)(sa_l + r0 * 80 + kb + 16);
            al[mi][3] = *(const uint32_t*)(sa_l + (r0 + 8) * 80 + kb + 16);
        }
#pragma unroll
        for (int ni = 0; ni < 4; ++ni) {
            int n0 = n0w + ni * 8 + g;
            uint32_t bh0 = *(const uint32_t*)(sb_h + n0 * 80 + kb);
            uint32_t bh1 = *(const uint32_t*)(sb_h + n0 * 80 + kb + 16);
            uint32_t bl0 = *(const uint32_t*)(sb_l + n0 * 80 + kb);
            uint32_t bl1 = *(const uint32_t*)(sb_l + n0 * 80 + kb + 16);
#pragma unroll
            for (int mi = 0; mi < 4; ++mi) {
                MMA_BF16(acc[mi][ni], ah[mi][0], ah[mi][1], ah[mi][2], ah[mi][3], bh0, bh1);
                MMA_BF16(acc[mi][ni], ah[mi][0], ah[mi][1], ah[mi][2], ah[mi][3], bl0, bl1);
                MMA_BF16(acc[mi][ni], al[mi][0], al[mi][1], al[mi][2], al[mi][3], bh0, bh1);
            }
        }
    }
}

__global__ __launch_bounds__(256, 1)
void hgemm2_kernel(const __nv_bfloat16* __restrict__ Ah, const __nv_bfloat16* __restrict__ Al,
                   const __nv_bfloat16* __restrict__ Bh, const __nv_bfloat16* __restrict__ Bl,
                   const float* __restrict__ bias, float* __restrict__ C,
                   int M, int N, int K)
{
    extern __shared__ __align__(16) char smem[];
    const int tid = threadIdx.x;
    const int warp = tid >> 5, lane = tid & 31;
    const int g = lane >> 2, tg = lane & 3;
    const int m0w = (warp >> 2) * 64;            // 0 | 64
    const int n0w = (warp & 3) * 32;             // 0..96
    const int bm = blockIdx.y * 128, bn = blockIdx.x * 128;
    const uint32_t sb = smem_u32(smem);

    float acc[4][4][4];
#pragma unroll
    for (int i = 0; i < 4; ++i)
#pragma unroll
        for (int j = 0; j < 4; ++j)
#pragma unroll
            for (int e = 0; e < 4; ++e) acc[i][j][e] = 0.f;

    const int nk = K >> 5;
    hg_load(sb, Ah, Al, Bh, Bl, bm, bn, K, 0, tid);
    CPA_COMMIT();
    for (int i = 0; i < nk; ++i) {
        if (i + 1 < nk) {
            hg_load(sb + ((i + 1) & 1) * 40960, Ah, Al, Bh, Bl, bm, bn, K, (i + 1) * 32, tid);
            CPA_COMMIT();
            CPA_WAIT1();
        } else {
            CPA_WAIT0();
        }
        __syncthreads();
        hg_compute(smem + (i & 1) * 40960, acc, m0w, n0w, g, tg);
        __syncthreads();
    }

#pragma unroll
    for (int mi = 0; mi < 4; ++mi) {
        int row = bm + m0w + mi * 16 + g;
#pragma unroll
        for (int ni = 0; ni < 4; ++ni) {
            int col = bn + n0w + ni * 8 + 2 * tg;
            float b0 = bias[col], b1 = bias[col + 1];
            *(float2*)&C[(size_t)row * N + col] =
                make_float2(acc[mi][ni][0] + b0, acc[mi][ni][1] + b1);
            *(float2*)&C[(size_t)(row + 8) * N + col] =
                make_float2(acc[mi][ni][2] + b0, acc[mi][ni][3] + b1);
        }
    }
}

// ---------------- c_t[r] = sum_l u_t[l] * B_t[l][r] (8 tokens/block) -------
__global__ __launch_bounds__(256) void c_kernel(const float* __restrict__ x)
{
    int t = blockIdx.x * 8 + (threadIdx.x >> 5);
    int r = threadIdx.x & 31;
    float u = x[(size_t)t * DD + r];           // lane l holds u_l
    const float* brow = g_Bmat + (size_t)t * 1024 + r * 32;
    float4 b4[8];
#pragma unroll
    for (int q = 0; q < 8; ++q) b4[q] = __ldg((const float4*)(brow + 4 * q));
    float c = 0.f;
#pragma unroll
    for (int q = 0; q < 8; ++q) {
        c = fmaf(__shfl_sync(0xffffffffu, u, 4 * q + 0), b4[q].x, c);
        c = fmaf(__shfl_sync(0xffffffffu, u, 4 * q + 1), b4[q].y, c);
        c = fmaf(__shfl_sync(0xffffffffu, u, 4 * q + 2), b4[q].z, c);
        c = fmaf(__shfl_sync(0xffffffffu, u, 4 * q + 3), b4[q].w, c);
    }
    g_c[(size_t)t * 32 + r] = c;
}

// ---------------- sequential scan: one warp per batch, prefetch depth 2 ----
__device__ __forceinline__ float scan_step(float v, const float4* BC, float cc,
                                           float uu, float* leftp)
{
    float w0 = 0.f, w1 = 0.f, w2 = 0.f, w3 = 0.f;
    float s0 = 0.f, s1 = 0.f, s2 = 0.f, s3 = 0.f;
#pragma unroll
    for (int q = 0; q < 8; q += 4) {
        float va, vb, vc, vd;
        va = __shfl_sync(0xffffffffu, v, 4*q + 0);
        vb = __shfl_sync(0xffffffffu, v, 4*q + 1);
        vc = __shfl_sync(0xffffffffu, v, 4*q + 2);
        vd = __shfl_sync(0xffffffffu, v, 4*q + 3);
        w0 = fmaf(va, BC[q].x, w0); s0 = fmaf(va, va, s0);
        w0 = fmaf(vb, BC[q].y, w0); s0 = fmaf(vb, vb, s0);
        w0 = fmaf(vc, BC[q].z, w0); s0 = fmaf(vc, vc, s0);
        w0 = fmaf(vd, BC[q].w, w0); s0 = fmaf(vd, vd, s0);
        va = __shfl_sync(0xffffffffu, v, 4*q + 4);
        vb = __shfl_sync(0xffffffffu, v, 4*q + 5);
        vc = __shfl_sync(0xffffffffu, v, 4*q + 6);
        vd = __shfl_sync(0xffffffffu, v, 4*q + 7);
        w1 = fmaf(va, BC[q+1].x, w1); s1 = fmaf(va, va, s1);
        w1 = fmaf(vb, BC[q+1].y, w1); s1 = fmaf(vb, vb, s1);
        w1 = fmaf(vc, BC[q+1].z, w1); s1 = fmaf(vc, vc, s1);
        w1 = fmaf(vd, BC[q+1].w, w1); s1 = fmaf(vd, vd, s1);
        va = __shfl_sync(0xffffffffu, v, 4*q + 8);
        vb = __shfl_sync(0xffffffffu, v, 4*q + 9);
        vc = __shfl_sync(0xffffffffu, v, 4*q + 10);
        vd = __shfl_sync(0xffffffffu, v, 4*q + 11);
        w2 = fmaf(va, BC[q+2].x, w2); s2 = fmaf(va, va, s2);
        w2 = fmaf(vb, BC[q+2].y, w2); s2 = fmaf(vb, vb, s2);
        w2 = fmaf(vc, BC[q+2].z, w2); s2 = fmaf(vc, vc, s2);
        w2 = fmaf(vd, BC[q+2].w, w2); s2 = fmaf(vd, vd, s2);
        va = __shfl_sync(0xffffffffu, v, 4*q + 12);
        vb = __shfl_sync(0xffffffffu, v, 4*q + 13);
        vc = __shfl_sync(0xffffffffu, v, 4*q + 14);
        vd = __shfl_sync(0xffffffffu, v, 4*q + 15);
        w3 = fmaf(va, BC[q+3].x, w3); s3 = fmaf(va, va, s3);
        w3 = fmaf(vb, BC[q+3].y, w3); s3 = fmaf(vb, vb, s3);
        w3 = fmaf(vc, BC[q+3].z, w3); s3 = fmaf(vc, vc, s3);
        w3 = fmaf(vd, BC[q+3].w, w3); s3 = fmaf(vd, vd, s3);
    }
    float w = (w0 + w1) + (w2 + w3);
    float s = (s0 + s1) + (s2 + s3);
    float alpha = rsqrtf(s + 1e-24f);          // s==0 -> alpha*v == 0 == h0
    *leftp = fmaf(alpha, v, uu);
    return fmaf(alpha, w, cc);
}

__global__ void scan_kernel(const float* __restrict__ x)
{
    const int b = blockIdx.x;
    const int r = threadIdx.x;                 // 0..31
    const size_t tg0 = (size_t)b * LL;
    const float* Bbase = g_Bmat + tg0 * 1024 + r * 32;
    const float* cbase = g_c + tg0 * 32 + r;
    const float* ubase = x + tg0 * DD + r;
    float* lp = g_left + tg0 * 32 + r;

    float4 b0[8], b1[8], b2[8];
    float c0, c1, c2, u0, u1, u2;

#define PREF(PT, BUF, CC, UU) { \
        int tp_ = (PT); if (tp_ > (LL-1)) tp_ = LL-1; \
        const float* bp_ = Bbase + (size_t)tp_ * 1024; \
        BUF[0] = __ldg((const float4*)(bp_ + 0));  BUF[1] = __ldg((const float4*)(bp_ + 4)); \
        BUF[2] = __ldg((const float4*)(bp_ + 8));  BUF[3] = __ldg((const float4*)(bp_ + 12)); \
        BUF[4] = __ldg((const float4*)(bp_ + 16)); BUF[5] = __ldg((const float4*)(bp_ + 20)); \
        BUF[6] = __ldg((const float4*)(bp_ + 24)); BUF[7] = __ldg((const float4*)(bp_ + 28)); \
        CC = __ldg(cbase + (size_t)tp_ * 32); \
        UU = __ldg(ubase + (size_t)tp_ * DD); }

    PREF(0, b0, c0, u0);
    PREF(1, b1, c1, u1);
    float v = 0.f;

#pragma unroll 1
    for (int t = 0; t < LL - 1; t += 3) {
        PREF(t + 2, b2, c2, u2);
        v = scan_step(v, b0, c0, u0, lp); lp += 32;
        PREF(t + 3, b0, c0, u0);
        v = scan_step(v, b1, c1, u1, lp); lp += 32;
        PREF(t + 4, b1, c1, u1);
        v = scan_step(v, b2, c2, u2, lp); lp += 32;
    }
    // main loop covers t = 0..1022 (341 blocks of 3); tail t = 1023 in b0
    v = scan_step(v, b0, c0, u0, lp);
#undef PREF
}

// ------- recover Mt per token; emit bf16 split for the final GEMM ----------
__global__ __launch_bounds__(128) void mrec_kernel()
{
    __shared__ float sleft[32];
    int t = blockIdx.x, tid = threadIdx.x;
    if (tid < 32) sleft[tid] = g_left[(size_t)t * 32 + tid];
    __syncthreads();
    const float* row = g_site + (size_t)t * CSC;
    float m = 0.f;
#pragma unroll
    for (int l = 0; l < 32; ++l)
        m = fmaf(sleft[l], __ldcs(row + l * 128 + tid), m);   // streaming, coalesced
    __nv_bfloat16 h, lo;
    bsplit(m, h, lo);
    g_mh[(size_t)t * 128 + tid] = h;
    g_ml[(size_t)t * 128 + tid] = lo;
}

// ---------------- LayerNorm + sigmoid-gated residual ----------------
__global__ __launch_bounds__(256) void post_kernel(const float* __restrict__ x,
                                                   const float* __restrict__ gamma,
                                                   const float* __restrict__ beta,
                                                   float* __restrict__ out)
{
    __shared__ float red[256];
    int t = blockIdx.x, tid = threadIdx.x;
    size_t base = (size_t)t * DD;
    int j0 = tid, j1 = tid + 256;
    float y0 = g_y[base + j0], y1 = g_y[base + j1];

    red[tid] = y0 + y1;
    __syncthreads();
    for (int st = 128; st > 0; st >>= 1) {
        if (tid < st) red[tid] += red[tid + st];
        __syncthreads();
    }
    float mu = red[0] * (1.f / 512.f);
    __syncthreads();

    float d0 = y0 - mu, d1 = y1 - mu;
    red[tid] = d0 * d0 + d1 * d1;
    __syncthreads();
    for (int st = 128; st > 0; st >>= 1) {
        if (tid < st) red[tid] += red[tid + st];
        __syncthreads();
    }
    float var = red[0] * (1.f / 512.f);
    float rstd = rsqrtf(var + 1e-6f);

    float yn0 = d0 * rstd * gamma[j0] + beta[j0];
    float yn1 = d1 * rstd * gamma[j1] + beta[j1];
    float gl0 = g_gate[base + j0], gl1 = g_gate[base + j1];
    float gt0 = 1.f / (1.f + expf(-gl0));
    float gt1 = 1.f / (1.f + expf(-gl1));
    float xv0 = x[base + j0], xv1 = x[base + j1];
    out[base + j0] = gt0 * yn0 + (1.f - gt0) * xv0;
    out[base + j1] = gt1 * yn1 + (1.f - gt1) * xv1;
}

// ---------------- launch ----------------
extern "C" void kernel_launch(void* const* d_in, const int* in_sizes, int n_in,
                              void* d_out, int out_size)
{
    (void)in_sizes; (void)n_in; (void)out_size;
    const float* x       = (const float*)d_in[0];
    const float* W_site  = (const float*)d_in[1];
    const float* b_site  = (const float*)d_in[2];
    const float* W_bridge= (const float*)d_in[3];
    const float* b_bridge= (const float*)d_in[4];
    const float* W_out   = (const float*)d_in[5];
    const float* b_out   = (const float*)d_in[6];
    const float* gamma   = (const float*)d_in[7];
    const float* beta    = (const float*)d_in[8];
    const float* W_gate  = (const float*)d_in[9];
    const float* b_gate  = (const float*)d_in[10];
    float* out = (float*)d_out;

    static float *p_site, *p_gate, *p_y, *p_WB, *p_bB, *p_Wco, *p_bco, *p_Bmat;
    static __nv_bfloat16 *p_xh, *p_xl, *p_WsTh, *p_WsTl, *p_WgTh, *p_WgTl,
                         *p_WBTh, *p_WBTl, *p_WcoTh, *p_WcoTl, *p_mh, *p_ml;
    static cudaStream_t s1;
    static cudaEvent_t ev0, evS, evG;
    static bool inited = false;
    if (!inited) {
        cudaGetSymbolAddress((void**)&p_site,  g_site);
        cudaGetSymbolAddress((void**)&p_gate,  g_gate);
        cudaGetSymbolAddress((void**)&p_y,     g_y);
        cudaGetSymbolAddress((void**)&p_WB,    g_WB);
        cudaGetSymbolAddress((void**)&p_bB,    g_bB);
        cudaGetSymbolAddress((void**)&p_Wco,   g_Wco);
        cudaGetSymbolAddress((void**)&p_bco,   g_bco);
        cudaGetSymbolAddress((void**)&p_Bmat,  g_Bmat);
        cudaGetSymbolAddress((void**)&p_xh,    g_xh);
        cudaGetSymbolAddress((void**)&p_xl,    g_xl);
        cudaGetSymbolAddress((void**)&p_WsTh,  g_WsT_h);
        cudaGetSymbolAddress((void**)&p_WsTl,  g_WsT_l);
        cudaGetSymbolAddress((void**)&p_WgTh,  g_WgT_h);
        cudaGetSymbolAddress((void**)&p_WgTl,  g_WgT_l);
        cudaGetSymbolAddress((void**)&p_WBTh,  g_WBT_h);
        cudaGetSymbolAddress((void**)&p_WBTl,  g_WBT_l);
        cudaGetSymbolAddress((void**)&p_WcoTh, g_WcoT_h);
        cudaGetSymbolAddress((void**)&p_WcoTl, g_WcoT_l);
        cudaGetSymbolAddress((void**)&p_mh,    g_mh);
        cudaGetSymbolAddress((void**)&p_ml,    g_ml);
        cudaStreamCreateWithFlags(&s1, cudaStreamNonBlocking);
        cudaEventCreateWithFlags(&ev0, cudaEventDisableTiming);
        cudaEventCreateWithFlags(&evS, cudaEventDisableTiming);
        cudaEventCreateWithFlags(&evG, cudaEventDisableTiming);
        cudaFuncSetAttribute(hgemm2_kernel, cudaFuncAttributeMaxDynamicSharedMemorySize, HG_SMEM);
        inited = true;
    }

    // shared prologue: x split (both branches need it)
    xcvt_kernel<<<(NT * DD) / 256, 256>>>(x);
    cudaEventRecord(ev0, 0);
    cudaStreamWaitEvent(s1, ev0, 0);

    // ---- side stream: prep + weight converts + site & gate GEMMs ----
    prep_kernel<<<256, 256, 0, s1>>>(W_bridge, b_bridge, W_out, b_out);
    tsplit_kernel<<<dim3(16, 4),  dim3(32, 8), 0, s1>>>(p_Wco,  p_WcoTh, p_WcoTl, 128, 512);
    tsplit_kernel<<<dim3(128,16), dim3(32, 8), 0, s1>>>(W_site, p_WsTh,  p_WsTl,  512, 4096);
    tsplit_kernel<<<dim3(16, 16), dim3(32, 8), 0, s1>>>(W_gate, p_WgTh,  p_WgTl,  512, 512);
    hgemm2_kernel<<<dim3(CSC/128, NT/128), 256, HG_SMEM, s1>>>(
        p_xh, p_xl, p_WsTh, p_WsTl, b_site, p_site, NT, CSC, DD);
    cudaEventRecord(evS, s1);
    hgemm2_kernel<<<dim3(DD/128, NT/128), 256, HG_SMEM, s1>>>(
        p_xh, p_xl, p_WgTh, p_WgTl, b_gate, p_gate, NT, DD, DD);
    cudaEventRecord(evG, s1);

    // ---- main stream: B-matrix path + scan ----
    wb_kernel<<<2048, 256>>>(W_site, b_site);
    tsplit_kernel<<<dim3(32, 16), dim3(32, 8)>>>(p_WB, p_WBTh, p_WBTl, 512, 1024);
    hgemm2_kernel<<<dim3(1024/128, NT/128), 256, HG_SMEM>>>(
        p_xh, p_xl, p_WBTh, p_WBTl, p_bB, p_Bmat, NT, 1024, DD);
    c_kernel<<<NT / 8, 256>>>(x);
    scan_kernel<<<BB, 32>>>(x);

    // join: site needed for M recovery, then final GEMM
    cudaStreamWaitEvent(0, evS, 0);
    mrec_kernel<<<NT, 128>>>();
    hgemm2_kernel<<<dim3(DD/128, NT/128), 256, HG_SMEM>>>(
        p_mh, p_ml, p_WcoTh, p_WcoTl, p_bco, p_y, NT, DD, 128);

    // join: gate needed for the epilogue
    cudaStreamWaitEvent(0, evG, 0);
    post_kernel<<<NT, 256>>>(x, gamma, beta, out);
}